// round 7
// baseline (speedup 1.0000x reference)
#include <cuda_runtime.h>
#include <cuda_fp16.h>
#include <cstdint>

// Problem constants
#define NN    8192
#define F_IN  512
#define F_OUT 256
#define ALPHA 0.2f
#define NEG_INF (-9e15f)
#define FLT_MAXN 3.402823466e38f

// -------- scratch (device globals: no allocations allowed) ----------------
__device__ float  g_h  [NN * F_OUT];  // h = x @ W (fp32, for f1/f2)
__device__ float  g_htT[F_OUT * NN];  // h^T, tf32-rounded: [col][row] (mma B)
__device__ float  g_f1[NN];
__device__ float  g_f2[NN];
__device__ float2 g_e2[NN];           // (exp(f2_j), exp(0.2*f2_j))
__device__ float4 g_rc[NN];           // per-row (A, C, Bthr, 1/l)

__device__ __forceinline__ float to_tf32(float x) {
    uint32_t r;
    asm("cvt.rna.tf32.f32 %0, %1;" : "=r"(r) : "f"(x));
    return __uint_as_float(r);
}

__device__ __forceinline__ uint32_t smem_u32(const void* p) {
    uint32_t a;
    asm("{ .reg .u64 t; cvta.to.shared.u64 t, %1; cvt.u32.u64 %0, t; }"
        : "=r"(a) : "l"(p));
    return a;
}

__device__ __forceinline__ void ldsm4(uint32_t& r0, uint32_t& r1,
                                      uint32_t& r2, uint32_t& r3, uint32_t addr) {
    asm volatile("ldmatrix.sync.aligned.m8n8.x4.shared.b16 {%0,%1,%2,%3}, [%4];"
                 : "=r"(r0), "=r"(r1), "=r"(r2), "=r"(r3) : "r"(addr));
}

// ===========================================================================
// Kernel 1: h = x @ W; writes fp32 h (row major) + tf32 h^T (col major)
// ===========================================================================
__global__ __launch_bounds__(256) void gemm1_kernel(
    const float* __restrict__ X, const float* __restrict__ W)
{
    __shared__ float Xs[16][64];
    __shared__ float Ws[16][64];
    __shared__ float tr[64][72];    // transpose buffer [col][row]

    const int t   = threadIdx.x;
    const int tx  = t & 15;
    const int ty  = t >> 4;
    const int row0 = blockIdx.x * 64;
    const int col0 = blockIdx.y * 64;

    float acc[4][4];
#pragma unroll
    for (int i = 0; i < 4; ++i)
#pragma unroll
        for (int j = 0; j < 4; ++j) acc[i][j] = 0.f;

    for (int k0 = 0; k0 < F_IN; k0 += 16) {
        {
            int r  = t >> 2;
            int kq = (t & 3) * 4;
            float4 v = *(const float4*)&X[(size_t)(row0 + r) * F_IN + k0 + kq];
            Xs[kq + 0][r] = v.x;
            Xs[kq + 1][r] = v.y;
            Xs[kq + 2][r] = v.z;
            Xs[kq + 3][r] = v.w;
        }
        {
            int kr = t >> 4;
            int cq = (t & 15) * 4;
            *(float4*)&Ws[kr][cq] =
                *(const float4*)&W[(size_t)(k0 + kr) * F_OUT + col0 + cq];
        }
        __syncthreads();

#pragma unroll
        for (int kk = 0; kk < 16; ++kk) {
            float a4[4], b4[4];
            *(float4*)a4 = *(const float4*)&Xs[kk][ty * 4];
            *(float4*)b4 = *(const float4*)&Ws[kk][tx * 4];
#pragma unroll
            for (int i = 0; i < 4; ++i)
#pragma unroll
                for (int j = 0; j < 4; ++j)
                    acc[i][j] = fmaf(a4[i], b4[j], acc[i][j]);
        }
        __syncthreads();
    }

#pragma unroll
    for (int i = 0; i < 4; ++i) {
        size_t off = (size_t)(row0 + ty * 4 + i) * F_OUT + col0 + tx * 4;
        *(float4*)&g_h[off] = make_float4(acc[i][0], acc[i][1], acc[i][2], acc[i][3]);
#pragma unroll
        for (int j = 0; j < 4; ++j)
            tr[tx * 4 + j][ty * 4 + i] = to_tf32(acc[i][j]);
    }
    __syncthreads();

    // coalesced write of tf32 h^T
    {
        int col = t >> 2;            // 0..63
        int r0  = (t & 3) * 16;      // 0,16,32,48
        size_t off = (size_t)(col0 + col) * NN + row0 + r0;
#pragma unroll
        for (int q = 0; q < 4; ++q)
            *(float4*)&g_htT[off + q * 4] = *(const float4*)&tr[col][r0 + q * 4];
    }
}

// ===========================================================================
// Kernel 2: f1 / f2 row dot products + e2 table
// ===========================================================================
__global__ __launch_bounds__(256) void f12_kernel(const float* __restrict__ a)
{
    const int warp = threadIdx.x >> 5;
    const int lane = threadIdx.x & 31;
    const int row  = blockIdx.x * 8 + warp;
    if (row >= NN) return;

    const float* hr = &g_h[(size_t)row * F_OUT];
    float s1 = 0.f, s2 = 0.f;
#pragma unroll
    for (int q = 0; q < 8; ++q) {
        int f = lane + q * 32;
        float v = hr[f];
        s1 = fmaf(v, a[f], s1);
        s2 = fmaf(v, a[F_OUT + f], s2);
    }
#pragma unroll
    for (int off = 16; off > 0; off >>= 1) {
        s1 += __shfl_xor_sync(0xffffffffu, s1, off);
        s2 += __shfl_xor_sync(0xffffffffu, s2, off);
    }
    if (lane == 0) {
        g_f1[row] = s1;
        g_f2[row] = s2;
        g_e2[row] = make_float2(__expf(s2), __expf(ALPHA * s2));
    }
}

// ===========================================================================
// Kernel 3: per-row constants: A, C, Bthr, 1/l  (exp-free inner loop)
//   m_i = lrelu(f1_i + max_adj f2_j);  l = A*S1 + C*S2
//   S1 = sum_{adj, f2>-f1} exp(f2_j);  S2 = sum_{adj, f2<=-f1} exp(.2 f2_j)
// ===========================================================================
__global__ __launch_bounds__(256) void rowstats_kernel(const int* __restrict__ adj)
{
    const int warp = threadIdx.x >> 5;
    const int lane = threadIdx.x & 31;
    const int row  = blockIdx.x * 8 + warp;

    const int* arow = adj + (size_t)row * NN;
    const float f1v = g_f1[row];
    const float thr = -f1v;

    float M2 = -FLT_MAXN;
    float S1 = 0.f, S2 = 0.f;

    for (int j0 = lane * 8; j0 < NN; j0 += 256) {
        int4   A0 = *(const int4*)&arow[j0];
        int4   A1 = *(const int4*)&arow[j0 + 4];
        float4 F0 = *(const float4*)&g_f2[j0];
        float4 F1 = *(const float4*)&g_f2[j0 + 4];
        float4 E0 = *(const float4*)&g_e2[j0];
        float4 E1 = *(const float4*)&g_e2[j0 + 2];
        float4 E2 = *(const float4*)&g_e2[j0 + 4];
        float4 E3 = *(const float4*)&g_e2[j0 + 6];

        int   av[8] = {A0.x, A0.y, A0.z, A0.w, A1.x, A1.y, A1.z, A1.w};
        float fv[8] = {F0.x, F0.y, F0.z, F0.w, F1.x, F1.y, F1.z, F1.w};
        float bv[8] = {E0.x, E0.z, E1.x, E1.z, E2.x, E2.z, E3.x, E3.z};
        float dv[8] = {E0.y, E0.w, E1.y, E1.w, E2.y, E2.w, E3.y, E3.w};
#pragma unroll
        for (int k = 0; k < 8; ++k) {
            bool msk = av[k] > 0;
            if (msk) M2 = fmaxf(M2, fv[k]);
            bool pos = fv[k] > thr;
            S1 += (msk && pos)  ? bv[k] : 0.f;
            S2 += (msk && !pos) ? dv[k] : 0.f;
        }
    }

#pragma unroll
    for (int off = 16; off > 0; off >>= 1) {
        M2 = fmaxf(M2, __shfl_xor_sync(0xffffffffu, M2, off));
        S1 += __shfl_xor_sync(0xffffffffu, S1, off);
        S2 += __shfl_xor_sync(0xffffffffu, S2, off);
    }
    if (lane == 0) {
        float A = 0.f, C = 0.f, il = 0.f;
        if (M2 > -FLT_MAXN) {
            float m = f1v + M2;
            m = (m > 0.f) ? m : ALPHA * m;
            A = __expf(f1v - m);
            C = __expf(ALPHA * f1v - m);
            float l = A * S1 + C * S2;
            il = (l > 0.f) ? 1.f / l : 0.f;
        }
        g_rc[row] = make_float4(A, C, __expf(thr), il);
    }
}

// ===========================================================================
// Kernel 4: att @ h via tf32 mma m16n8k8, ldmatrix fragments, pipelined.
// 256 threads (8 warps), BM=32 (grid 256), j-tile 32, double buffered.
// h_s stored [n][k] so both A and B frags come from ldmatrix.x4.
// ===========================================================================
#define BM2    32
#define BN2    32
#define NT     (NN / BN2)           // 256 tiles
#define PS     36                   // p_s row stride (floats)
#define KS     36                   // h_s row stride (floats)
#define HBUF_F (256 * KS)           // floats per h buffer
#define PBUF_F (BM2 * PS)           // floats per p buffer
#define SMEM_BYTES ((2 * HBUF_F + 2 * PBUF_F) * 4)

__global__ __launch_bounds__(256) void gat_mma_kernel(
    const int* __restrict__ adj, float* __restrict__ out)
{
    extern __shared__ float smemf[];
    float* h_s = smemf;                  // [2][256][KS]
    float* p_s = smemf + 2 * HBUF_F;     // [2][BM2][PS]
    const uint32_t h_a = smem_u32(h_s);
    const uint32_t p_a = smem_u32(p_s);

    const int t    = threadIdx.x;
    const int warp = t >> 5;
    const int lane = t & 31;
    const int rowbase = blockIdx.x * BM2;

    // mma mapping: warp covers 32 rows x cols [warp*32, warp*32+32)
    const int ncol = warp * 32;
    const int gr   = lane >> 2;
    const int tg   = lane & 3;

    // ldmatrix lane offsets (floats)
    const int lrow = lane & 7;
    const int lp8  = (lane >> 3) & 1;   // +8 rows for A
    const int lc4  = (lane >> 4) & 1;   // +4 cols for A
    // A: matrix idx = lane>>3: {r0-7 c0-3},{r8-15 c0-3},{r0-7 c4-7},{r8-15 c4-7}
    int aoff[2];
#pragma unroll
    for (int mt = 0; mt < 2; ++mt)
        aoff[mt] = (mt * 16 + lp8 * 8 + lrow) * PS + lc4 * 4;
    // B: matrix idx = k-group 0..3: boff + idx*4
    int boff[4];
#pragma unroll
    for (int nt = 0; nt < 4; ++nt)
        boff[nt] = (ncol + nt * 8 + lrow) * KS + ((lane >> 3) * 4);

    // p-build mapping: thread -> row pr, 4 j at pj
    const int pr = t >> 3;
    const int pj = (t & 7) * 4;
    const float4 rc = g_rc[rowbase + pr];     // (A, C, Bthr, il)
    const int* arow = adj + (size_t)(rowbase + pr) * NN;

    float c[2][4][4];
#pragma unroll
    for (int mt = 0; mt < 2; ++mt)
#pragma unroll
        for (int nt = 0; nt < 4; ++nt)
#pragma unroll
            for (int q = 0; q < 4; ++q) c[mt][nt][q] = 0.f;

    // ---------------- prologue: tile 0 p + h ---------------------------
    float4 phv;
    {
        int4   A0 = *(const int4*)&arow[pj];
        float4 E0 = *(const float4*)&g_e2[pj];
        float4 E1 = *(const float4*)&g_e2[pj + 2];
        int   av[4] = {A0.x, A0.y, A0.z, A0.w};
        float bv[4] = {E0.x, E0.z, E1.x, E1.z};
        float dv[4] = {E0.y, E0.w, E1.y, E1.w};
        float pv[4];
#pragma unroll
        for (int k = 0; k < 4; ++k) {
            bool cond = bv[k] > rc.z;
            float p = (cond ? bv[k] : dv[k]) * (cond ? rc.x : rc.y);
            pv[k] = to_tf32((av[k] > 0) ? p : 0.f);
        }
        phv = make_float4(pv[0], pv[1], pv[2], pv[3]);
    }
    {
        const float* src = &g_htT[(size_t)t * NN];
        uint32_t dst = h_a + (uint32_t)(t * KS) * 4;
#pragma unroll
        for (int q = 0; q < 8; ++q)
            asm volatile("cp.async.cg.shared.global [%0], [%1], 16;\n"
                         :: "r"(dst + q * 16), "l"(src + q * 4));
        asm volatile("cp.async.commit_group;\n" ::: "memory");
    }

    // ---------------- main loop ----------------------------------------
    for (int it = 0; it < NT; ++it) {
        const int buf = it & 1;
        const bool more = (it + 1 < NT);
        int4   nA;
        float4 nE0, nE1;

        if (more) {
            int jn = (it + 1) * BN2;
            const float* src = &g_htT[(size_t)t * NN + jn];
            uint32_t dst = h_a + (uint32_t)((buf ^ 1) * HBUF_F + t * KS) * 4;
#pragma unroll
            for (int q = 0; q < 8; ++q)
                asm volatile("cp.async.cg.shared.global [%0], [%1], 16;\n"
                             :: "r"(dst + q * 16), "l"(src + q * 4));
            asm volatile("cp.async.commit_group;\n" ::: "memory");
            nA  = *(const int4*)&arow[jn + pj];
            nE0 = *(const float4*)&g_e2[jn + pj];
            nE1 = *(const float4*)&g_e2[jn + pj + 2];
        }

        *(float4*)&p_s[buf * PBUF_F + pr * PS + pj] = phv;

        if (more) asm volatile("cp.async.wait_group 1;\n" ::: "memory");
        else      asm volatile("cp.async.wait_group 0;\n" ::: "memory");
        __syncthreads();

        // ---- fragments via ldmatrix, then mma ---------------------------
        const uint32_t pbase = p_a + (uint32_t)(buf * PBUF_F) * 4;
        const uint32_t hbase = h_a + (uint32_t)(buf * HBUF_F) * 4;

        uint32_t A_[8][4];                      // [mt*4+ks][frag]
#pragma unroll
        for (int ks = 0; ks < 4; ++ks) {
#pragma unroll
            for (int mt = 0; mt < 2; ++mt)
                ldsm4(A_[mt * 4 + ks][0], A_[mt * 4 + ks][1],
                      A_[mt * 4 + ks][2], A_[mt * 4 + ks][3],
                      pbase + (uint32_t)(aoff[mt] + ks * 8) * 4);
        }

#pragma unroll
        for (int nt = 0; nt < 4; ++nt) {
            uint32_t B_[8];
            ldsm4(B_[0], B_[1], B_[2], B_[3], hbase + (uint32_t)boff[nt] * 4);
            ldsm4(B_[4], B_[5], B_[6], B_[7], hbase + (uint32_t)boff[nt] * 4 + 64);
#pragma unroll
            for (int ks = 0; ks < 4; ++ks) {
#pragma unroll
                for (int mt = 0; mt < 2; ++mt) {
                    asm volatile(
                        "mma.sync.aligned.m16n8k8.row.col.f32.tf32.tf32.f32 "
                        "{%0,%1,%2,%3}, {%4,%5,%6,%7}, {%8,%9}, {%0,%1,%2,%3};"
                        : "+f"(c[mt][nt][0]), "+f"(c[mt][nt][1]),
                          "+f"(c[mt][nt][2]), "+f"(c[mt][nt][3])
                        : "r"(A_[mt * 4 + ks][0]), "r"(A_[mt * 4 + ks][1]),
                          "r"(A_[mt * 4 + ks][2]), "r"(A_[mt * 4 + ks][3]),
                          "r"(B_[2 * ks]), "r"(B_[2 * ks + 1]));
                }
            }
        }

        // ---- build next tile's p ---------------------------------------
        if (more) {
            int   av[4] = {nA.x, nA.y, nA.z, nA.w};
            float bv[4] = {nE0.x, nE0.z, nE1.x, nE1.z};
            float dv[4] = {nE0.y, nE0.w, nE1.y, nE1.w};
            float pv[4];
#pragma unroll
            for (int k = 0; k < 4; ++k) {
                bool cond = bv[k] > rc.z;
                float p = (cond ? bv[k] : dv[k]) * (cond ? rc.x : rc.y);
                pv[k] = to_tf32((av[k] > 0) ? p : 0.f);
            }
            phv = make_float4(pv[0], pv[1], pv[2], pv[3]);
        }
    }

    // ---- epilogue: normalize by 1/l, ELU, store -----------------------
#pragma unroll
    for (int mt = 0; mt < 2; ++mt) {
        int row0 = rowbase + mt * 16 + gr;
        int row1 = row0 + 8;
        float il0 = g_rc[row0].w;
        float il1 = g_rc[row1].w;
#pragma unroll
        for (int nt = 0; nt < 4; ++nt) {
            int col = ncol + nt * 8 + tg * 2;
            float v0 = c[mt][nt][0] * il0, v1 = c[mt][nt][1] * il0;
            float v2 = c[mt][nt][2] * il1, v3 = c[mt][nt][3] * il1;
            v0 = (v0 > 0.f) ? v0 : (__expf(v0) - 1.f);
            v1 = (v1 > 0.f) ? v1 : (__expf(v1) - 1.f);
            v2 = (v2 > 0.f) ? v2 : (__expf(v2) - 1.f);
            v3 = (v3 > 0.f) ? v3 : (__expf(v3) - 1.f);
            *(float2*)&out[(size_t)row0 * F_OUT + col] = make_float2(v0, v1);
            *(float2*)&out[(size_t)row1 * F_OUT + col] = make_float2(v2, v3);
        }
    }
}

// ===========================================================================
// launch
// ===========================================================================
extern "C" void kernel_launch(void* const* d_in, const int* in_sizes, int n_in,
                              void* d_out, int out_size)
{
    const float* x   = (const float*)d_in[0];   // [8192, 512]
    const int*   adj = (const int*)  d_in[1];   // [8192, 8192]
    const float* W   = (const float*)d_in[2];   // [512, 256]
    const float* a   = (const float*)d_in[3];   // [512, 1]
    float* out = (float*)d_out;                 // [8192, 256]

    cudaFuncSetAttribute(gat_mma_kernel,
                         cudaFuncAttributeMaxDynamicSharedMemorySize, SMEM_BYTES);

    gemm1_kernel<<<dim3(NN / 64, F_OUT / 64), 256>>>(x, W);
    f12_kernel<<<NN / 8, 256>>>(a);
    rowstats_kernel<<<NN / 8, 256>>>(adj);
    gat_mma_kernel<<<NN / BM2, 256, SMEM_BYTES>>>(adj, out);
}

// round 10
// speedup vs baseline: 1.6617x; 1.6617x over previous
#include <cuda_runtime.h>
#include <cuda_fp16.h>
#include <cstdint>

// Problem constants
#define NN    8192
#define F_IN  512
#define F_OUT 256
#define ALPHA 0.2f
#define NEG_INF (-9e15f)
#define FLT_MAXN 3.402823466e38f

// -------- scratch (device globals: no allocations allowed) ----------------
__device__ float  g_h [NN * F_OUT];   // h = x @ W (fp32, for f1/f2)
__device__ float  g_ht[NN * F_OUT];   // h tf32-rounded, ROW major (mma B src)
__device__ float  g_f1[NN];
__device__ float  g_f2[NN];
__device__ float2 g_e2[NN];           // (exp(f2_j), exp(0.2*f2_j))
__device__ float4 g_rc[NN];           // per-row (A, C, Bthr, 1/l)

__device__ __forceinline__ float to_tf32(float x) {
    uint32_t r;
    asm("cvt.rna.tf32.f32 %0, %1;" : "=r"(r) : "f"(x));
    return __uint_as_float(r);
}

__device__ __forceinline__ uint32_t smem_u32(const void* p) {
    uint32_t a;
    asm("{ .reg .u64 t; cvta.to.shared.u64 t, %1; cvt.u32.u64 %0, t; }"
        : "=r"(a) : "l"(p));
    return a;
}

__device__ __forceinline__ void ldsm4(uint32_t& r0, uint32_t& r1,
                                      uint32_t& r2, uint32_t& r3, uint32_t addr) {
    asm volatile("ldmatrix.sync.aligned.m8n8.x4.shared.b16 {%0,%1,%2,%3}, [%4];"
                 : "=r"(r0), "=r"(r1), "=r"(r2), "=r"(r3) : "r"(addr));
}

// ===========================================================================
// Kernel 1: h = x @ W  (8192x512 @ 512x256); fp32 h + tf32-rounded row-major
// ===========================================================================
__global__ __launch_bounds__(256) void gemm1_kernel(
    const float* __restrict__ X, const float* __restrict__ W)
{
    __shared__ float Xs[16][64];
    __shared__ float Ws[16][64];

    const int t   = threadIdx.x;
    const int tx  = t & 15;
    const int ty  = t >> 4;
    const int row0 = blockIdx.x * 64;
    const int col0 = blockIdx.y * 64;

    float acc[4][4];
#pragma unroll
    for (int i = 0; i < 4; ++i)
#pragma unroll
        for (int j = 0; j < 4; ++j) acc[i][j] = 0.f;

    for (int k0 = 0; k0 < F_IN; k0 += 16) {
        {
            int r  = t >> 2;
            int kq = (t & 3) * 4;
            float4 v = *(const float4*)&X[(size_t)(row0 + r) * F_IN + k0 + kq];
            Xs[kq + 0][r] = v.x;
            Xs[kq + 1][r] = v.y;
            Xs[kq + 2][r] = v.z;
            Xs[kq + 3][r] = v.w;
        }
        {
            int kr = t >> 4;
            int cq = (t & 15) * 4;
            *(float4*)&Ws[kr][cq] =
                *(const float4*)&W[(size_t)(k0 + kr) * F_OUT + col0 + cq];
        }
        __syncthreads();

#pragma unroll
        for (int kk = 0; kk < 16; ++kk) {
            float a4[4], b4[4];
            *(float4*)a4 = *(const float4*)&Xs[kk][ty * 4];
            *(float4*)b4 = *(const float4*)&Ws[kk][tx * 4];
#pragma unroll
            for (int i = 0; i < 4; ++i)
#pragma unroll
                for (int j = 0; j < 4; ++j)
                    acc[i][j] = fmaf(a4[i], b4[j], acc[i][j]);
        }
        __syncthreads();
    }

#pragma unroll
    for (int i = 0; i < 4; ++i) {
        size_t off = (size_t)(row0 + ty * 4 + i) * F_OUT + col0 + tx * 4;
        *(float4*)&g_h[off]  = make_float4(acc[i][0], acc[i][1], acc[i][2], acc[i][3]);
        *(float4*)&g_ht[off] = make_float4(to_tf32(acc[i][0]), to_tf32(acc[i][1]),
                                           to_tf32(acc[i][2]), to_tf32(acc[i][3]));
    }
}

// ===========================================================================
// Kernel 2: f1 / f2 row dot products + e2 table
// ===========================================================================
__global__ __launch_bounds__(256) void f12_kernel(const float* __restrict__ a)
{
    const int warp = threadIdx.x >> 5;
    const int lane = threadIdx.x & 31;
    const int row  = blockIdx.x * 8 + warp;
    if (row >= NN) return;

    const float* hr = &g_h[(size_t)row * F_OUT];
    float s1 = 0.f, s2 = 0.f;
#pragma unroll
    for (int q = 0; q < 8; ++q) {
        int f = lane + q * 32;
        float v = hr[f];
        s1 = fmaf(v, a[f], s1);
        s2 = fmaf(v, a[F_OUT + f], s2);
    }
#pragma unroll
    for (int off = 16; off > 0; off >>= 1) {
        s1 += __shfl_xor_sync(0xffffffffu, s1, off);
        s2 += __shfl_xor_sync(0xffffffffu, s2, off);
    }
    if (lane == 0) {
        g_f1[row] = s1;
        g_f2[row] = s2;
        g_e2[row] = make_float2(__expf(s2), __expf(ALPHA * s2));
    }
}

// ===========================================================================
// Kernel 3: per-row constants (A, C, Bthr, 1/l) — exp-free inner loop
// ===========================================================================
__global__ __launch_bounds__(256) void rowstats_kernel(const int* __restrict__ adj)
{
    const int warp = threadIdx.x >> 5;
    const int lane = threadIdx.x & 31;
    const int row  = blockIdx.x * 8 + warp;

    const int* arow = adj + (size_t)row * NN;
    const float f1v = g_f1[row];
    const float thr = -f1v;

    float M2 = -FLT_MAXN;
    float S1 = 0.f, S2 = 0.f;

    for (int j0 = lane * 8; j0 < NN; j0 += 256) {
        int4   A0 = *(const int4*)&arow[j0];
        int4   A1 = *(const int4*)&arow[j0 + 4];
        float4 F0 = *(const float4*)&g_f2[j0];
        float4 F1 = *(const float4*)&g_f2[j0 + 4];
        float4 E0 = *(const float4*)&g_e2[j0];
        float4 E1 = *(const float4*)&g_e2[j0 + 2];
        float4 E2 = *(const float4*)&g_e2[j0 + 4];
        float4 E3 = *(const float4*)&g_e2[j0 + 6];

        int   av[8] = {A0.x, A0.y, A0.z, A0.w, A1.x, A1.y, A1.z, A1.w};
        float fv[8] = {F0.x, F0.y, F0.z, F0.w, F1.x, F1.y, F1.z, F1.w};
        float bv[8] = {E0.x, E0.z, E1.x, E1.z, E2.x, E2.z, E3.x, E3.z};
        float dv[8] = {E0.y, E0.w, E1.y, E1.w, E2.y, E2.w, E3.y, E3.w};
#pragma unroll
        for (int k = 0; k < 8; ++k) {
            bool msk = av[k] > 0;
            if (msk) M2 = fmaxf(M2, fv[k]);
            bool pos = fv[k] > thr;
            S1 += (msk && pos)  ? bv[k] : 0.f;
            S2 += (msk && !pos) ? dv[k] : 0.f;
        }
    }

#pragma unroll
    for (int off = 16; off > 0; off >>= 1) {
        M2 = fmaxf(M2, __shfl_xor_sync(0xffffffffu, M2, off));
        S1 += __shfl_xor_sync(0xffffffffu, S1, off);
        S2 += __shfl_xor_sync(0xffffffffu, S2, off);
    }
    if (lane == 0) {
        float A = 0.f, C = 0.f, il = 0.f;
        if (M2 > -FLT_MAXN) {
            float m = f1v + M2;
            m = (m > 0.f) ? m : ALPHA * m;
            A = __expf(f1v - m);
            C = __expf(ALPHA * f1v - m);
            float l = A * S1 + C * S2;
            il = (l > 0.f) ? 1.f / l : 0.f;
        }
        g_rc[row] = make_float4(A, C, __expf(thr), il);
    }
}

// ===========================================================================
// Kernel 4: att @ h via tf32 mma m16n8k8, pipelined, double-buffered.
// A fragments via ldmatrix.x4 from p_s [m][k]; B scalar from h_s [k][n].
// TWO barriers per tile: the tail barrier is required — without it, the
// cp.async prefetch for tile it+1 (issued before the head barrier) races
// with lagging warps still reading tile it-1 from the same buffer.
// ===========================================================================
#define BM2    32
#define BN2    32
#define NT     (NN / BN2)           // 256 tiles
#define PS     36                   // p_s row stride (floats)
#define HS     264                  // h_s row stride (floats)
#define HBUF_F (BN2 * HS)           // 8448 floats per h buffer
#define PBUF_F (BM2 * PS)           // 1152 floats per p buffer
#define SMEM_BYTES ((2 * HBUF_F + 2 * PBUF_F) * 4)

__global__ __launch_bounds__(256) void gat_mma_kernel(
    const int* __restrict__ adj, float* __restrict__ out)
{
    extern __shared__ float smemf[];
    float* h_s = smemf;                  // [2][BN2][HS]  (k-major: [k][n])
    float* p_s = smemf + 2 * HBUF_F;     // [2][BM2][PS]  (m-major: [m][k])
    const uint32_t h_a = smem_u32(h_s);
    const uint32_t p_a = smem_u32(p_s);

    const int t    = threadIdx.x;
    const int warp = t >> 5;
    const int lane = t & 31;
    const int rowbase = blockIdx.x * BM2;

    // mma mapping: warp covers 32 rows x cols [warp*32, warp*32+32)
    const int ncol = warp * 32;
    const int gr   = lane >> 2;
    const int tg   = lane & 3;

    // ldmatrix lane offsets for A (p_s [m][k], tf32-as-b16 trick)
    const int lrow = lane & 7;
    const int lp8  = (lane >> 3) & 1;
    const int lc4  = (lane >> 4) & 1;
    int aoff[2];
#pragma unroll
    for (int mt = 0; mt < 2; ++mt)
        aoff[mt] = (mt * 16 + lp8 * 8 + lrow) * PS + lc4 * 4;

    // p-build mapping: thread -> row pr, 4 j at pj
    const int pr = t >> 3;
    const int pj = (t & 7) * 4;
    const float4 rc = g_rc[rowbase + pr];      // (A, C, Bthr, il)
    const int* arow = adj + (size_t)(rowbase + pr) * NN;

    float c[2][4][4];
#pragma unroll
    for (int mt = 0; mt < 2; ++mt)
#pragma unroll
        for (int nt = 0; nt < 4; ++nt)
#pragma unroll
            for (int q = 0; q < 4; ++q) c[mt][nt][q] = 0.f;

    // ---------------- prologue: tile 0 ---------------------------------
    float4 phv;
    {
        int4   A0 = *(const int4*)&arow[pj];
        float4 E0 = *(const float4*)&g_e2[pj];
        float4 E1 = *(const float4*)&g_e2[pj + 2];
        int   av[4] = {A0.x, A0.y, A0.z, A0.w};
        float bv[4] = {E0.x, E0.z, E1.x, E1.z};
        float dv[4] = {E0.y, E0.w, E1.y, E1.w};
        float pv[4];
#pragma unroll
        for (int k = 0; k < 4; ++k) {
            bool cond = bv[k] > rc.z;
            float p = (cond ? bv[k] : dv[k]) * (cond ? rc.x : rc.y);
            pv[k] = to_tf32((av[k] > 0) ? p : 0.f);
        }
        phv = make_float4(pv[0], pv[1], pv[2], pv[3]);
    }
    // cp.async h tile 0 into buffer 0 (row-major g_ht, coalesced)
    {
#pragma unroll
        for (int q = 0; q < 8; ++q) {
            int fi = q * 256 + t;            // float4 idx 0..2047
            int jj = fi >> 6;
            int ff = (fi & 63) * 4;
            uint32_t dst = h_a + (uint32_t)(jj * HS + ff) * 4;
            const float* src = &g_ht[(size_t)jj * F_OUT + ff];
            asm volatile("cp.async.cg.shared.global [%0], [%1], 16;\n"
                         :: "r"(dst), "l"(src));
        }
        asm volatile("cp.async.commit_group;\n" ::: "memory");
    }

    // ---------------- main loop ----------------------------------------
    for (int it = 0; it < NT; ++it) {
        const int buf = it & 1;
        const bool more = (it + 1 < NT);
        int4   nA;
        float4 nE0, nE1;

        if (more) {
            int jn = (it + 1) * BN2;
#pragma unroll
            for (int q = 0; q < 8; ++q) {
                int fi = q * 256 + t;
                int jj = fi >> 6;
                int ff = (fi & 63) * 4;
                uint32_t dst = h_a + (uint32_t)((buf ^ 1) * HBUF_F + jj * HS + ff) * 4;
                const float* src = &g_ht[(size_t)(jn + jj) * F_OUT + ff];
                asm volatile("cp.async.cg.shared.global [%0], [%1], 16;\n"
                             :: "r"(dst), "l"(src));
            }
            asm volatile("cp.async.commit_group;\n" ::: "memory");
            nA  = *(const int4*)&arow[jn + pj];
            nE0 = *(const float4*)&g_e2[jn + pj];
            nE1 = *(const float4*)&g_e2[jn + pj + 2];
        }

        *(float4*)&p_s[buf * PBUF_F + pr * PS + pj] = phv;

        if (more) asm volatile("cp.async.wait_group 1;\n" ::: "memory");
        else      asm volatile("cp.async.wait_group 0;\n" ::: "memory");
        __syncthreads();

        // ---- tensor-core GEMM on this tile -----------------------------
        const float* hb = &h_s[buf * HBUF_F];
        const uint32_t pbase = p_a + (uint32_t)(buf * PBUF_F) * 4;
#pragma unroll
        for (int ks = 0; ks < 4; ++ks) {
            int kb = ks * 8;
            uint32_t Af[2][4];
            ldsm4(Af[0][0], Af[0][1], Af[0][2], Af[0][3],
                  pbase + (uint32_t)(aoff[0] + kb) * 4);
            ldsm4(Af[1][0], Af[1][1], Af[1][2], Af[1][3],
                  pbase + (uint32_t)(aoff[1] + kb) * 4);
#pragma unroll
            for (int nt = 0; nt < 4; ++nt) {
                int n0 = ncol + nt * 8 + gr;
                uint32_t b0 = __float_as_uint(hb[(kb + tg)     * HS + n0]);
                uint32_t b1 = __float_as_uint(hb[(kb + tg + 4) * HS + n0]);
#pragma unroll
                for (int mt = 0; mt < 2; ++mt) {
                    asm volatile(
                        "mma.sync.aligned.m16n8k8.row.col.f32.tf32.tf32.f32 "
                        "{%0,%1,%2,%3}, {%4,%5,%6,%7}, {%8,%9}, {%0,%1,%2,%3};"
                        : "+f"(c[mt][nt][0]), "+f"(c[mt][nt][1]),
                          "+f"(c[mt][nt][2]), "+f"(c[mt][nt][3])
                        : "r"(Af[mt][0]), "r"(Af[mt][1]),
                          "r"(Af[mt][2]), "r"(Af[mt][3]),
                          "r"(b0), "r"(b1));
                }
            }
        }

        // ---- build next tile's p (exp-free) ----------------------------
        if (more) {
            int   av[4] = {nA.x, nA.y, nA.z, nA.w};
            float bv[4] = {nE0.x, nE0.z, nE1.x, nE1.z};
            float dv[4] = {nE0.y, nE0.w, nE1.y, nE1.w};
            float pv[4];
#pragma unroll
            for (int k = 0; k < 4; ++k) {
                bool cond = bv[k] > rc.z;
                float p = (cond ? bv[k] : dv[k]) * (cond ? rc.x : rc.y);
                pv[k] = to_tf32((av[k] > 0) ? p : 0.f);
            }
            phv = make_float4(pv[0], pv[1], pv[2], pv[3]);
        }

        // tail barrier: all warps done READING buffers (mma smem reads +
        // ldsm) before any warp's next-iteration cp.async / p-store WRITES
        // into them. Removing this reintroduces the replay-divergence race.
        __syncthreads();
    }

    // ---- epilogue: normalize by 1/l, ELU, store -----------------------
#pragma unroll
    for (int mt = 0; mt < 2; ++mt) {
        int row0 = rowbase + mt * 16 + gr;
        int row1 = row0 + 8;
        float il0 = g_rc[row0].w;
        float il1 = g_rc[row1].w;
#pragma unroll
        for (int nt = 0; nt < 4; ++nt) {
            int col = ncol + nt * 8 + tg * 2;
            float v0 = c[mt][nt][0] * il0, v1 = c[mt][nt][1] * il0;
            float v2 = c[mt][nt][2] * il1, v3 = c[mt][nt][3] * il1;
            v0 = (v0 > 0.f) ? v0 : (__expf(v0) - 1.f);
            v1 = (v1 > 0.f) ? v1 : (__expf(v1) - 1.f);
            v2 = (v2 > 0.f) ? v2 : (__expf(v2) - 1.f);
            v3 = (v3 > 0.f) ? v3 : (__expf(v3) - 1.f);
            *(float2*)&out[(size_t)row0 * F_OUT + col] = make_float2(v0, v1);
            *(float2*)&out[(size_t)row1 * F_OUT + col] = make_float2(v2, v3);
        }
    }
}

// ===========================================================================
// launch
// ===========================================================================
extern "C" void kernel_launch(void* const* d_in, const int* in_sizes, int n_in,
                              void* d_out, int out_size)
{
    const float* x   = (const float*)d_in[0];   // [8192, 512]
    const int*   adj = (const int*)  d_in[1];   // [8192, 8192]
    const float* W   = (const float*)d_in[2];   // [512, 256]
    const float* a   = (const float*)d_in[3];   // [512, 1]
    float* out = (float*)d_out;                 // [8192, 256]

    cudaFuncSetAttribute(gat_mma_kernel,
                         cudaFuncAttributeMaxDynamicSharedMemorySize, SMEM_BYTES);

    gemm1_kernel<<<dim3(NN / 64, F_OUT / 64), 256>>>(x, W);
    f12_kernel<<<NN / 8, 256>>>(a);
    rowstats_kernel<<<NN / 8, 256>>>(adj);
    gat_mma_kernel<<<NN / BM2, 256, SMEM_BYTES>>>(adj, out);
}

// round 12
// speedup vs baseline: 1.8695x; 1.1251x over previous
#include <cuda_runtime.h>
#include <cuda_fp16.h>
#include <cstdint>

// Problem constants
#define NN    8192
#define F_IN  512
#define F_OUT 256
#define ALPHA 0.2f
#define NEG_INF (-9e15f)
#define FLT_MAXN 3.402823466e38f

// -------- scratch (device globals: no allocations allowed) ----------------
__device__ float   g_h [NN * F_OUT];   // h = x @ W (fp32, for f1/f2)
__device__ float   g_ht[NN * F_OUT];   // h tf32-rounded, ROW major (mma B src)
__device__ float   g_f1[NN];
__device__ float   g_f2[NN];
__device__ float2  g_e2[NN];           // (exp(f2_j), exp(0.2*f2_j))
__device__ float4  g_rc[NN];           // per-row (A, C, Bthr, 1/l)
__device__ uint8_t g_bits[NN * (NN / 8)];  // packed adj>0 bits (8 MB)

__device__ __forceinline__ float to_tf32(float x) {
    uint32_t r;
    asm("cvt.rna.tf32.f32 %0, %1;" : "=r"(r) : "f"(x));
    return __uint_as_float(r);
}

__device__ __forceinline__ uint32_t smem_u32(const void* p) {
    uint32_t a;
    asm("{ .reg .u64 t; cvta.to.shared.u64 t, %1; cvt.u32.u64 %0, t; }"
        : "=r"(a) : "l"(p));
    return a;
}

__device__ __forceinline__ void ldsm4(uint32_t& r0, uint32_t& r1,
                                      uint32_t& r2, uint32_t& r3, uint32_t addr) {
    asm volatile("ldmatrix.sync.aligned.m8n8.x4.shared.b16 {%0,%1,%2,%3}, [%4];"
                 : "=r"(r0), "=r"(r1), "=r"(r2), "=r"(r3) : "r"(addr));
}

// ===========================================================================
// Kernel 1: h = x @ W  (8192x512 @ 512x256); fp32 h + tf32-rounded row-major
// ===========================================================================
__global__ __launch_bounds__(256) void gemm1_kernel(
    const float* __restrict__ X, const float* __restrict__ W)
{
    __shared__ float Xs[16][64];
    __shared__ float Ws[16][64];

    const int t   = threadIdx.x;
    const int tx  = t & 15;
    const int ty  = t >> 4;
    const int row0 = blockIdx.x * 64;
    const int col0 = blockIdx.y * 64;

    float acc[4][4];
#pragma unroll
    for (int i = 0; i < 4; ++i)
#pragma unroll
        for (int j = 0; j < 4; ++j) acc[i][j] = 0.f;

    for (int k0 = 0; k0 < F_IN; k0 += 16) {
        {
            int r  = t >> 2;
            int kq = (t & 3) * 4;
            float4 v = *(const float4*)&X[(size_t)(row0 + r) * F_IN + k0 + kq];
            Xs[kq + 0][r] = v.x;
            Xs[kq + 1][r] = v.y;
            Xs[kq + 2][r] = v.z;
            Xs[kq + 3][r] = v.w;
        }
        {
            int kr = t >> 4;
            int cq = (t & 15) * 4;
            *(float4*)&Ws[kr][cq] =
                *(const float4*)&W[(size_t)(k0 + kr) * F_OUT + col0 + cq];
        }
        __syncthreads();

#pragma unroll
        for (int kk = 0; kk < 16; ++kk) {
            float a4[4], b4[4];
            *(float4*)a4 = *(const float4*)&Xs[kk][ty * 4];
            *(float4*)b4 = *(const float4*)&Ws[kk][tx * 4];
#pragma unroll
            for (int i = 0; i < 4; ++i)
#pragma unroll
                for (int j = 0; j < 4; ++j)
                    acc[i][j] = fmaf(a4[i], b4[j], acc[i][j]);
        }
        __syncthreads();
    }

#pragma unroll
    for (int i = 0; i < 4; ++i) {
        size_t off = (size_t)(row0 + ty * 4 + i) * F_OUT + col0 + tx * 4;
        *(float4*)&g_h[off]  = make_float4(acc[i][0], acc[i][1], acc[i][2], acc[i][3]);
        *(float4*)&g_ht[off] = make_float4(to_tf32(acc[i][0]), to_tf32(acc[i][1]),
                                           to_tf32(acc[i][2]), to_tf32(acc[i][3]));
    }
}

// ===========================================================================
// Kernel 2: f1 / f2 row dot products + e2 table
// ===========================================================================
__global__ __launch_bounds__(256) void f12_kernel(const float* __restrict__ a)
{
    const int warp = threadIdx.x >> 5;
    const int lane = threadIdx.x & 31;
    const int row  = blockIdx.x * 8 + warp;
    if (row >= NN) return;

    const float* hr = &g_h[(size_t)row * F_OUT];
    float s1 = 0.f, s2 = 0.f;
#pragma unroll
    for (int q = 0; q < 8; ++q) {
        int f = lane + q * 32;
        float v = hr[f];
        s1 = fmaf(v, a[f], s1);
        s2 = fmaf(v, a[F_OUT + f], s2);
    }
#pragma unroll
    for (int off = 16; off > 0; off >>= 1) {
        s1 += __shfl_xor_sync(0xffffffffu, s1, off);
        s2 += __shfl_xor_sync(0xffffffffu, s2, off);
    }
    if (lane == 0) {
        g_f1[row] = s1;
        g_f2[row] = s2;
        g_e2[row] = make_float2(__expf(s2), __expf(ALPHA * s2));
    }
}

// ===========================================================================
// Kernel 3: rowstats — streams adj + f2 ONLY. Online (m, l) softmax stats,
// emits rc = (A, C, Bthr, 1/l) and the packed adjacency bits.
// ===========================================================================
__global__ __launch_bounds__(256) void rowstats_kernel(const int* __restrict__ adj)
{
    const int warp = threadIdx.x >> 5;
    const int lane = threadIdx.x & 31;
    const int row  = blockIdx.x * 8 + warp;

    const int* arow = adj + (size_t)row * NN;
    uint8_t* brow   = g_bits + (size_t)row * (NN / 8);
    const float f1v = g_f1[row];

    float m = -FLT_MAXN;
    float l = 0.f;

    for (int j0 = lane * 8; j0 < NN; j0 += 256) {
        int4   A0 = *(const int4*)&arow[j0];
        int4   A1 = *(const int4*)&arow[j0 + 4];
        float4 F0 = *(const float4*)&g_f2[j0];
        float4 F1 = *(const float4*)&g_f2[j0 + 4];

        int   av[8] = {A0.x, A0.y, A0.z, A0.w, A1.x, A1.y, A1.z, A1.w};
        float fv[8] = {F0.x, F0.y, F0.z, F0.w, F1.x, F1.y, F1.z, F1.w};
        float sv[8];
        uint32_t bits = 0;
#pragma unroll
        for (int k = 0; k < 8; ++k) {
            float e = f1v + fv[k];
            e = (e > 0.f) ? e : ALPHA * e;
            bool msk = av[k] > 0;
            sv[k] = msk ? e : NEG_INF;
            bits |= (msk ? 1u : 0u) << k;
        }
        brow[j0 >> 3] = (uint8_t)bits;      // coalesced across lanes

        float cm = sv[0];
#pragma unroll
        for (int k = 1; k < 8; ++k) cm = fmaxf(cm, sv[k]);
        float mn = fmaxf(m, cm);
        float s = 0.f;
#pragma unroll
        for (int k = 0; k < 8; ++k) s += __expf(sv[k] - mn);
        l = l * __expf(m - mn) + s;
        m = mn;
    }

#pragma unroll
    for (int off = 16; off > 0; off >>= 1) {
        float m2 = __shfl_xor_sync(0xffffffffu, m, off);
        float l2 = __shfl_xor_sync(0xffffffffu, l, off);
        float mn = fmaxf(m, m2);
        l = l * __expf(m - mn) + l2 * __expf(m2 - mn);
        m = mn;
    }
    if (lane == 0) {
        float A = 0.f, C = 0.f, il = 0.f;
        if (l > 0.f) {
            A  = __expf(f1v - m);
            C  = __expf(ALPHA * f1v - m);
            il = 1.f / l;
        }
        g_rc[row] = make_float4(A, C, __expf(-f1v), il);
    }
}

// ===========================================================================
// Kernel 4: att @ h via tf32 mma m16n8k8. BM=64 rows/CTA (grid 128) to halve
// L2 h-traffic; adjacency from packed bits (8 MB total, not 268 MB).
// 512 threads (16 warps): warp grid 2m x 8n, warp tile 32 rows x 32 cols.
// Double-buffered cp.async h tiles; exp-free p-build; two barriers/tile.
// ===========================================================================
#define BM2    64
#define BN2    32
#define NT     (NN / BN2)           // 256 tiles
#define PS     36                   // p_s row stride (floats)
#define HS     264                  // h_s row stride (floats)
#define HBUF_F (BN2 * HS)           // 8448 floats per h buffer
#define PBUF_F (BM2 * PS)           // 2304 floats per p buffer
#define SMEM_BYTES ((2 * HBUF_F + 2 * PBUF_F) * 4)

__global__ __launch_bounds__(512) void gat_mma_kernel(float* __restrict__ out)
{
    extern __shared__ float smemf[];
    float* h_s = smemf;                  // [2][BN2][HS]  ([k][n])
    float* p_s = smemf + 2 * HBUF_F;     // [2][BM2][PS]  ([m][k])
    const uint32_t h_a = smem_u32(h_s);
    const uint32_t p_a = smem_u32(p_s);

    const int t    = threadIdx.x;
    const int warp = t >> 5;
    const int lane = t & 31;
    const int rowbase = blockIdx.x * BM2;

    // mma mapping: warp (w&1) selects 32-row half, (w>>1) selects 32 cols
    const int mrow = (warp & 1) * 32;
    const int ncol = (warp >> 1) * 32;
    const int gr   = lane >> 2;
    const int tg   = lane & 3;

    // ldmatrix lane offsets for A (p_s [m][k], tf32-as-b16 trick)
    const int lrow = lane & 7;
    const int lp8  = (lane >> 3) & 1;
    const int lc4  = (lane >> 4) & 1;
    int aoff[2];
#pragma unroll
    for (int mt = 0; mt < 2; ++mt)
        aoff[mt] = (mrow + mt * 16 + lp8 * 8 + lrow) * PS + lc4 * 4;

    // p-build mapping: thread -> row pr (0..63), 4 j at pj
    const int pr = t >> 3;
    const int pj = (t & 7) * 4;
    const float4 rc = g_rc[rowbase + pr];      // (A, C, Bthr, il)
    const uint8_t* brow = g_bits + (size_t)(rowbase + pr) * (NN / 8);

    float c[2][4][4];                // [m-tile][n-tile][frag]
#pragma unroll
    for (int mt = 0; mt < 2; ++mt)
#pragma unroll
        for (int nt = 0; nt < 4; ++nt)
#pragma unroll
            for (int q = 0; q < 4; ++q) c[mt][nt][q] = 0.f;

    // ---------------- prologue: tile 0 ---------------------------------
    float4 phv;
    {
        uint32_t w = *(const uint32_t*)&brow[0];
        float4 E0 = *(const float4*)&g_e2[pj];
        float4 E1 = *(const float4*)&g_e2[pj + 2];
        float bv[4] = {E0.x, E0.z, E1.x, E1.z};
        float dv[4] = {E0.y, E0.w, E1.y, E1.w};
        float pv[4];
#pragma unroll
        for (int k = 0; k < 4; ++k) {
            bool msk = (w >> (pj + k)) & 1u;
            bool cond = bv[k] > rc.z;
            float p = (cond ? bv[k] : dv[k]) * (cond ? rc.x : rc.y);
            pv[k] = to_tf32(msk ? p : 0.f);
        }
        phv = make_float4(pv[0], pv[1], pv[2], pv[3]);
    }
    // cp.async h tile 0 into buffer 0 (512 threads, 4 float4 each)
    {
#pragma unroll
        for (int q = 0; q < 4; ++q) {
            int fi = q * 512 + t;            // float4 idx 0..2047
            int jj = fi >> 6;
            int ff = (fi & 63) * 4;
            uint32_t dst = h_a + (uint32_t)(jj * HS + ff) * 4;
            const float* src = &g_ht[(size_t)jj * F_OUT + ff];
            asm volatile("cp.async.cg.shared.global [%0], [%1], 16;\n"
                         :: "r"(dst), "l"(src));
        }
        asm volatile("cp.async.commit_group;\n" ::: "memory");
    }

    // ---------------- main loop ----------------------------------------
    for (int it = 0; it < NT; ++it) {
        const int buf = it & 1;
        const bool more = (it + 1 < NT);
        uint32_t nW = 0;
        float4 nE0, nE1;

        if (more) {
            int jn = (it + 1) * BN2;
#pragma unroll
            for (int q = 0; q < 4; ++q) {
                int fi = q * 512 + t;
                int jj = fi >> 6;
                int ff = (fi & 63) * 4;
                uint32_t dst = h_a + (uint32_t)((buf ^ 1) * HBUF_F + jj * HS + ff) * 4;
                const float* src = &g_ht[(size_t)(jn + jj) * F_OUT + ff];
                asm volatile("cp.async.cg.shared.global [%0], [%1], 16;\n"
                             :: "r"(dst), "l"(src));
            }
            asm volatile("cp.async.commit_group;\n" ::: "memory");
            nW  = *(const uint32_t*)&brow[jn >> 3];
            nE0 = *(const float4*)&g_e2[jn + pj];
            nE1 = *(const float4*)&g_e2[jn + pj + 2];
        }

        *(float4*)&p_s[buf * PBUF_F + pr * PS + pj] = phv;

        if (more) asm volatile("cp.async.wait_group 1;\n" ::: "memory");
        else      asm volatile("cp.async.wait_group 0;\n" ::: "memory");
        __syncthreads();

        // ---- tensor-core GEMM on this tile -----------------------------
        const float* hb = &h_s[buf * HBUF_F];
        const uint32_t pbase = p_a + (uint32_t)(buf * PBUF_F) * 4;
#pragma unroll
        for (int ks = 0; ks < 4; ++ks) {
            int kb = ks * 8;
            uint32_t Af[2][4];
            ldsm4(Af[0][0], Af[0][1], Af[0][2], Af[0][3],
                  pbase + (uint32_t)(aoff[0] + kb) * 4);
            ldsm4(Af[1][0], Af[1][1], Af[1][2], Af[1][3],
                  pbase + (uint32_t)(aoff[1] + kb) * 4);
#pragma unroll
            for (int nt = 0; nt < 4; ++nt) {
                int n0 = ncol + nt * 8 + gr;
                uint32_t b0 = __float_as_uint(hb[(kb + tg)     * HS + n0]);
                uint32_t b1 = __float_as_uint(hb[(kb + tg + 4) * HS + n0]);
#pragma unroll
                for (int mt = 0; mt < 2; ++mt) {
                    asm volatile(
                        "mma.sync.aligned.m16n8k8.row.col.f32.tf32.tf32.f32 "
                        "{%0,%1,%2,%3}, {%4,%5,%6,%7}, {%8,%9}, {%0,%1,%2,%3};"
                        : "+f"(c[mt][nt][0]), "+f"(c[mt][nt][1]),
                          "+f"(c[mt][nt][2]), "+f"(c[mt][nt][3])
                        : "r"(Af[mt][0]), "r"(Af[mt][1]),
                          "r"(Af[mt][2]), "r"(Af[mt][3]),
                          "r"(b0), "r"(b1));
                }
            }
        }

        // ---- build next tile's p (exp-free, from bits) -----------------
        if (more) {
            float bv[4] = {nE0.x, nE0.z, nE1.x, nE1.z};
            float dv[4] = {nE0.y, nE0.w, nE1.y, nE1.w};
            float pv[4];
#pragma unroll
            for (int k = 0; k < 4; ++k) {
                bool msk = (nW >> (pj + k)) & 1u;
                bool cond = bv[k] > rc.z;
                float p = (cond ? bv[k] : dv[k]) * (cond ? rc.x : rc.y);
                pv[k] = to_tf32(msk ? p : 0.f);
            }
            phv = make_float4(pv[0], pv[1], pv[2], pv[3]);
        }

        // tail barrier: all warps finished READING both smem buffers before
        // any warp's next-iteration writes. Required for correctness.
        __syncthreads();
    }

    // ---- epilogue: normalize by 1/l, ELU, store -----------------------
#pragma unroll
    for (int mt = 0; mt < 2; ++mt) {
        int row0 = rowbase + mrow + mt * 16 + gr;
        int row1 = row0 + 8;
        float il0 = g_rc[row0].w;
        float il1 = g_rc[row1].w;
#pragma unroll
        for (int nt = 0; nt < 4; ++nt) {
            int col = ncol + nt * 8 + tg * 2;
            float v0 = c[mt][nt][0] * il0, v1 = c[mt][nt][1] * il0;
            float v2 = c[mt][nt][2] * il1, v3 = c[mt][nt][3] * il1;
            v0 = (v0 > 0.f) ? v0 : (__expf(v0) - 1.f);
            v1 = (v1 > 0.f) ? v1 : (__expf(v1) - 1.f);
            v2 = (v2 > 0.f) ? v2 : (__expf(v2) - 1.f);
            v3 = (v3 > 0.f) ? v3 : (__expf(v3) - 1.f);
            *(float2*)&out[(size_t)row0 * F_OUT + col] = make_float2(v0, v1);
            *(float2*)&out[(size_t)row1 * F_OUT + col] = make_float2(v2, v3);
        }
    }
}

// ===========================================================================
// launch
// ===========================================================================
extern "C" void kernel_launch(void* const* d_in, const int* in_sizes, int n_in,
                              void* d_out, int out_size)
{
    const float* x   = (const float*)d_in[0];   // [8192, 512]
    const int*   adj = (const int*)  d_in[1];   // [8192, 8192]
    const float* W   = (const float*)d_in[2];   // [512, 256]
    const float* a   = (const float*)d_in[3];   // [512, 1]
    float* out = (float*)d_out;                 // [8192, 256]

    cudaFuncSetAttribute(gat_mma_kernel,
                         cudaFuncAttributeMaxDynamicSharedMemorySize, SMEM_BYTES);

    gemm1_kernel<<<dim3(NN / 64, F_OUT / 64), 256>>>(x, W);
    f12_kernel<<<NN / 8, 256>>>(a);
    rowstats_kernel<<<NN / 8, 256>>>(adj);
    gat_mma_kernel<<<NN / BM2, 512, SMEM_BYTES>>>(out);
}